// round 11
// baseline (speedup 1.0000x reference)
#include <cuda_runtime.h>
#include <cuda_bf16.h>
#include <math.h>

#define T_STEPS 16384
#define N_DIM   256
#define M_DIM   512
#define G3      1536   // 3*M
#define NADDR   512    // K_MEM+1
#define L_OUT   256

#define CSZ     16     // cluster size (CTAs)
#define DPC     32     // h-dims per CTA (512/16)
#define NTHR    512

// ---------------- device scratch (static, no allocation) ----------------
__device__ __align__(16) float d_Gi[T_STEPS * G3];     // X @ W_ih^T + b_ih
__device__ __align__(16) float d_H [T_STEPS * M_DIM];  // h_out history
__device__ __align__(16) float d_M [NADDR * M_DIM];    // memory rows (write-once)
__device__ __align__(16) float d_Gc[NADDR * G3];       // cached gh: [q][3*d + gate]

// ---------------- helpers ----------------
__device__ __forceinline__ float ldcg_f(const float* p) {
    float v; asm volatile("ld.global.cg.f32 %0, [%1];" : "=f"(v) : "l"(p) : "memory"); return v;
}
__device__ __forceinline__ void stasync_u64(unsigned long long* lptr, unsigned long long* lmbar,
                                            unsigned rank, unsigned long long v) {
    unsigned la = (unsigned)__cvta_generic_to_shared(lptr);
    unsigned lm = (unsigned)__cvta_generic_to_shared(lmbar);
    unsigned ra, rm;
    asm volatile("mapa.shared::cluster.u32 %0, %1, %2;" : "=r"(ra) : "r"(la), "r"(rank));
    asm volatile("mapa.shared::cluster.u32 %0, %1, %2;" : "=r"(rm) : "r"(lm), "r"(rank));
    asm volatile("st.async.weak.shared::cluster.mbarrier::complete_tx::bytes.b64 [%0], %1, [%2];"
                 :: "r"(ra), "l"(v), "r"(rm) : "memory");
}
// bulk SMEM->remote-SMEM copy, completion tx-accounted on the REMOTE mbarrier
__device__ __forceinline__ void bulk_s2s(float* ldst, const float* lsrc,
                                         unsigned long long* lmbar,
                                         unsigned rank, unsigned bytes) {
    unsigned ld = (unsigned)__cvta_generic_to_shared(ldst);
    unsigned ls = (unsigned)__cvta_generic_to_shared(lsrc);
    unsigned lm = (unsigned)__cvta_generic_to_shared(lmbar);
    unsigned rd, rm;
    asm volatile("mapa.shared::cluster.u32 %0, %1, %2;" : "=r"(rd) : "r"(ld), "r"(rank));
    asm volatile("mapa.shared::cluster.u32 %0, %1, %2;" : "=r"(rm) : "r"(lm), "r"(rank));
    asm volatile("cp.async.bulk.shared::cluster.shared::cta.mbarrier::complete_tx::bytes "
                 "[%0], [%1], %2, [%3];"
                 :: "r"(rd), "r"(ls), "r"(bytes), "r"(rm) : "memory");
}
__device__ __forceinline__ void mbar_init(unsigned long long* m, unsigned cnt) {
    unsigned a = (unsigned)__cvta_generic_to_shared(m);
    asm volatile("mbarrier.init.shared.b64 [%0], %1;" :: "r"(a), "r"(cnt) : "memory");
}
__device__ __forceinline__ void mbar_expect_tx(unsigned long long* m, unsigned bytes) {
    unsigned a = (unsigned)__cvta_generic_to_shared(m);
    asm volatile("mbarrier.arrive.expect_tx.shared.b64 _, [%0], %1;" :: "r"(a), "r"(bytes) : "memory");
}
__device__ __forceinline__ void mbar_wait(unsigned long long* m, unsigned parity) {
    unsigned a = (unsigned)__cvta_generic_to_shared(m);
    unsigned done;
    asm volatile("{\n\t.reg .pred p;\n\t"
                 "mbarrier.try_wait.parity.acquire.cta.shared::cta.b64 p, [%1], %2;\n\t"
                 "selp.b32 %0, 1, 0, p;\n\t}"
                 : "=r"(done) : "r"(a), "r"(parity) : "memory");
    if (!done) {
        asm volatile("{\n\t.reg .pred P1;\n\t"
                     "WL_%=:\n\t"
                     "mbarrier.try_wait.parity.acquire.cta.shared::cta.b64 P1, [%0], %1, 0x989680;\n\t"
                     "@P1 bra.uni WD_%=;\n\t"
                     "bra.uni WL_%=;\n\t"
                     "WD_%=:\n\t}"
                     :: "r"(a), "r"(parity) : "memory");
    }
}
#define CLUSTER_SYNC() do { \
    asm volatile("barrier.cluster.arrive.aligned;" ::: "memory"); \
    asm volatile("barrier.cluster.wait.aligned;"   ::: "memory"); } while (0)

// lexicographic u64 max over lanes via two integer REDUX (exact, same winner
// as a shfl-based u64 max tree): max hi, then max lo among hi-winners.
__device__ __forceinline__ unsigned long long warp_max_key(unsigned long long k) {
    unsigned hi = (unsigned)(k >> 32);
    unsigned lo = (unsigned)k;
    unsigned mhi = __reduce_max_sync(0xFFFFFFFFu, hi);
    unsigned mlo = __reduce_max_sync(0xFFFFFFFFu, (hi == mhi) ? lo : 0u);
    return ((unsigned long long)mhi << 32) | mlo;
}

// ---------------- textbook 32x32 tiled NT GEMM (known good) ----------------
__global__ __launch_bounds__(1024) void gemm32_nt(
    const float* __restrict__ A, const float* __restrict__ B,
    const float* __restrict__ bias, float* __restrict__ C,
    int M, int N, int K)
{
    __shared__ float As[32][33];
    __shared__ float Bs[32][33];
    const int bm = blockIdx.y * 32;
    const int bn = blockIdx.x * 32;
    const int tx = threadIdx.x;
    const int ty = threadIdx.y;
    float acc = 0.f;
    for (int k0 = 0; k0 < K; k0 += 32) {
        As[ty][tx] = A[(size_t)(bm + ty) * K + k0 + tx];
        Bs[ty][tx] = B[(size_t)(bn + ty) * K + k0 + tx];
        __syncthreads();
        #pragma unroll
        for (int k = 0; k < 32; k++)
            acc = fmaf(As[ty][k], Bs[tx][k], acc);
        __syncthreads();
    }
    C[(size_t)(bm + ty) * N + bn + tx] = acc + bias[bn + tx];
}

// ---------------- clustered recurrent kernel ----------------
// Round-10 architecture + (1) d_H writeback moved into the hn-flight window,
// (2) REDUX-based key reduces, (3) dense 8-chain FMA block with spec trees
// filling the key-exchange window. All per-value arithmetic verbatim ->
// trajectory bit-identical to rounds 4/6/8/9/10.
__global__ __launch_bounds__(NTHR, 1) void dmm_rec(
    const float* __restrict__ h0,
    const float* __restrict__ W_hh,
    const float* __restrict__ b_hh,
    const float* __restrict__ C_w,
    const float* __restrict__ C_b)
{
    extern __shared__ float W_sm[];                 // [2*DPC][512]: z rows, n rows
    __shared__ __align__(16) float hn_sm[2][M_DIM]; // bulk-copy target (double buffer)
    __shared__ __align__(16) float stage_sm[2][DPC];// local h_new slice (bulk source)
    __shared__ unsigned long long wkey_sm[16];
    __shared__ unsigned long long ckey_sm[CSZ];     // st.async target
    __shared__ unsigned char written_w[16][NADDR];  // per-warp replicas of 'written'
    __shared__ unsigned long long mbar_hn, mbar_key;

    const int c   = blockIdx.x;                     // cluster rank (single cluster)
    const int tid = threadIdx.x;
    const int w   = tid >> 5;
    const int l   = tid & 31;
    const int ml  = l & 15;
    const int d0  = DPC * c + w;
    const int d1  = DPC * c + 16 + w;
    const int myd = (l < 16) ? d0 : d1;

    // ---- one-time init ----
    for (int idx = tid; idx < 2 * DPC * M_DIM; idx += NTHR) {
        int g   = idx >> 14;
        int rem = idx & 16383;
        int lr  = rem >> 9;
        int col = rem & 511;
        W_sm[idx] = W_hh[(size_t)((g + 1) * M_DIM + DPC * c + lr) * M_DIM + col];
    }
    for (int idx = tid; idx < 16 * NADDR; idx += NTHR)
        written_w[idx >> 9][idx & 511] = 0;
    if (tid == 0) {
        mbar_init(&mbar_hn, 1);
        mbar_init(&mbar_key, 1);
        asm volatile("fence.mbarrier_init.release.cluster;" ::: "memory");
    }

    float4 wr0[4], wr1[4], cw0[4], cw1[4];
    #pragma unroll
    for (int cch = 0; cch < 4; cch++) {
        wr0[cch] = *(const float4*)&W_hh[(size_t)d0 * M_DIM + cch * 128 + 4 * l];
        wr1[cch] = *(const float4*)&W_hh[(size_t)d1 * M_DIM + cch * 128 + 4 * l];
        cw0[cch] = *(const float4*)&C_w [(size_t)d0 * M_DIM + cch * 128 + 4 * l];
        cw1[cch] = *(const float4*)&C_w [(size_t)d1 * M_DIM + cch * 128 + 4 * l];
    }
    const float cb0 = C_b[d0], cb1 = C_b[d1];
    const float bhr = b_hh[myd], bhz = b_hh[M_DIM + myd], bhn = b_hh[2 * M_DIM + myd];

    // ---- bootstrap: spec dots on h0 ----
    if (tid < M_DIM) hn_sm[1][tid] = h0[tid];
    __syncthreads();

    float4 nv[4];
    #pragma unroll
    for (int cch = 0; cch < 4; cch++) nv[cch] = *(const float4*)&hn_sm[1][cch * 128 + 4 * l];

    // per-lane accumulation chain (no tree) — verbatim op order
    auto chain_sm = [&](const float* __restrict__ row) -> float {
        float acc = 0.f;
        #pragma unroll
        for (int cch = 0; cch < 4; cch++) {
            float4 wv = *(const float4*)&row[cch * 128 + 4 * l];
            acc = fmaf(wv.x, nv[cch].x, fmaf(wv.y, nv[cch].y,
                  fmaf(wv.z, nv[cch].z, fmaf(wv.w, nv[cch].w, acc))));
        }
        return acc;
    };
    auto chain_rg = [&](const float4* wreg) -> float {
        float acc = 0.f;
        #pragma unroll
        for (int cch = 0; cch < 4; cch++) {
            acc = fmaf(wreg[cch].x, nv[cch].x, fmaf(wreg[cch].y, nv[cch].y,
                  fmaf(wreg[cch].z, nv[cch].z, fmaf(wreg[cch].w, nv[cch].w, acc))));
        }
        return acc;
    };
    auto tree = [&](float acc) -> float {
        #pragma unroll
        for (int o = 16; o > 0; o >>= 1) acc += __shfl_xor_sync(0xFFFFFFFFu, acc, o);
        return acc;
    };

    float s0z = tree(chain_sm(&W_sm[(0 * DPC + w)      * M_DIM]));
    float s0n = tree(chain_sm(&W_sm[(1 * DPC + w)      * M_DIM]));
    float s1z = tree(chain_sm(&W_sm[(0 * DPC + 16 + w) * M_DIM]));
    float s1n = tree(chain_sm(&W_sm[(1 * DPC + 16 + w) * M_DIM]));
    float s0r = tree(chain_rg(wr0));
    float s1r = tree(chain_rg(wr1));

    float gr = (l < 16) ? s0r : s1r;
    float gz = (l < 16) ? s0z : s1z;
    float gn = (l < 16) ? s0n : s1n;
    float hp = hn_sm[1][myd];
    float gir = 0.f, giz = 0.f, gin = 0.f;
    if (ml == 0) {
        gir = __ldg(&d_Gi[myd]);
        giz = __ldg(&d_Gi[M_DIM + myd]);
        gin = __ldg(&d_Gi[2 * M_DIM + myd]);
    }

    // previous-step writeback state
    int pq = -1, phas = 0, ptb = 0;

    __syncthreads();
    CLUSTER_SYNC();   // mbarriers + SMEM init visible cluster-wide before async traffic

    for (int t = 0; t < T_STEPS; t++) {
        const int tb = t & 1;
        const unsigned par = (unsigned)(t & 1);

        // ---------- gates (lanes 0,16), verbatim expressions ----------
        float hnewv = 0.f;
        if (ml == 0) {
            float hr = gr + bhr, hz = gz + bhz, hn = gn + bhn;
            float rg = 1.f / (1.f + expf(-(gir + hr)));
            float zg = 1.f / (1.f + expf(-(giz + hz)));
            float ng = tanhf(gin + rg * hn);
            hnewv = (1.f - zg) * ng + zg * hp;
            stage_sm[tb][w + ((l < 16) ? 0 : 16)] = hnewv;   // contiguous 128B slice
        }
        const float v0 = __shfl_sync(0xFFFFFFFFu, hnewv, 0);
        const float v1 = __shfl_sync(0xFFFFFFFFu, hnewv, 16);
        __syncthreads();   // stage slice complete

        // ---------- bulk-deliver slice to all 16 ranks (warp 0, 16 x 128B) ----------
        if (tid == 0) mbar_expect_tx(&mbar_hn, M_DIM * 4u);     // 2048 B per phase
        if (w == 0 && l < CSZ) {
            asm volatile("fence.proxy.async.shared::cta;" ::: "memory");
            bulk_s2s(&hn_sm[tb][DPC * c], &stage_sm[tb][0], &mbar_hn,
                     (unsigned)l, DPC * 4u);
        }

        // ---------- hn-flight window: prev-step d_H writeback + Gi prefetch ----------
        if (pq >= 0 && c == ((t - 1) & (CSZ - 1))) {
            float hv_out = phas ? ldcg_f(&d_M[(size_t)pq * M_DIM + tid])
                                : hn_sm[ptb][tid];
            d_H[(size_t)(t - 1) * M_DIM + tid] = hv_out;
        }
        float ngir = 0.f, ngiz = 0.f, ngin = 0.f;
        if (ml == 0 && t + 1 < T_STEPS) {
            const float* g = &d_Gi[(size_t)(t + 1) * G3];
            ngir = __ldg(&g[myd]);
            ngiz = __ldg(&g[M_DIM + myd]);
            ngin = __ldg(&g[2 * M_DIM + myd]);
        }

        mbar_wait(&mbar_hn, par);   // all 16 slices landed locally

        // ---------- dense 8-chain FMA block ----------
        #pragma unroll
        for (int cch = 0; cch < 4; cch++) nv[cch] = *(const float4*)&hn_sm[tb][cch * 128 + 4 * l];
        float p0  = chain_rg(cw0);
        float p1  = chain_rg(cw1);
        float pz0 = chain_sm(&W_sm[(0 * DPC + w)      * M_DIM]);
        float pn0 = chain_sm(&W_sm[(1 * DPC + w)      * M_DIM]);
        float pz1 = chain_sm(&W_sm[(0 * DPC + 16 + w) * M_DIM]);
        float pn1 = chain_sm(&W_sm[(1 * DPC + 16 + w) * M_DIM]);
        float pr0 = chain_rg(wr0);
        float pr1 = chain_rg(wr1);

        // ---------- logit trees -> CTA key -> send ----------
        float acc0 = tree(p0);
        float acc1 = tree(p1);
        if (l == 0) {
            unsigned int u0 = __float_as_uint(acc0 + cb0);
            u0 ^= (u0 & 0x80000000u) ? 0xFFFFFFFFu : 0x80000000u;
            unsigned long long k0 = ((unsigned long long)u0 << 32) | (unsigned int)(1023 - d0);
            unsigned int u1 = __float_as_uint(acc1 + cb1);
            u1 ^= (u1 & 0x80000000u) ? 0xFFFFFFFFu : 0x80000000u;
            unsigned long long k1 = ((unsigned long long)u1 << 32) | (unsigned int)(1023 - d1);
            wkey_sm[w] = (k0 > k1) ? k0 : k1;
        }
        __syncthreads();
        if (tid == 0) mbar_expect_tx(&mbar_key, CSZ * 8u);      // 128 B per phase
        if (w == 0) {
            unsigned long long best = warp_max_key((l < 16) ? wkey_sm[l] : 0ull);
            if (l < CSZ) stasync_u64(&ckey_sm[c], &mbar_key, (unsigned)l, best);
        }

        // ---------- spec trees fill the key-exchange window ----------
        s0z = tree(pz0);
        s0n = tree(pn0);
        s1z = tree(pz1);
        s1n = tree(pn1);
        s0r = tree(pr0);
        s1r = tree(pr1);

        mbar_wait(&mbar_key, par);   // all 16 CTA keys landed locally

        // ---------- per-warp redundant decision (REDUX, no syncthreads) ----------
        unsigned long long best = warp_max_key((l < CSZ) ? ckey_sm[l] : 0ull);
        const int q   = 1023 - (int)(best & 0xFFFFFFFFull);
        const int has = (q > 0) && (written_w[w][q] != 0);
        __syncwarp();
        if (l == 0 && q > 0) written_w[w][q] = 1;

        // ---------- select next gate inputs + cache maintenance ----------
        const float s_r = (l < 16) ? s0r : s1r;
        const float s_z = (l < 16) ? s0z : s1z;
        const float s_n = (l < 16) ? s0n : s1n;
        const float hnw = (l < 16) ? v0  : v1;

        if (ml == 0) {
            if (has) {   // CTA-private cached slices (immutable after write)
                gr = __ldg(&d_Gc[(size_t)q * G3 + 3 * myd + 0]);
                gz = __ldg(&d_Gc[(size_t)q * G3 + 3 * myd + 1]);
                gn = __ldg(&d_Gc[(size_t)q * G3 + 3 * myd + 2]);
                hp = __ldg(&d_M [(size_t)q * M_DIM + myd]);
            } else {
                gr = s_r; gz = s_z; gn = s_n; hp = hnw;
            }
            if (!has && q > 0) {
                d_Gc[(size_t)q * G3 + 3 * myd + 0] = s_r;
                d_Gc[(size_t)q * G3 + 3 * myd + 1] = s_z;
                d_Gc[(size_t)q * G3 + 3 * myd + 2] = s_n;
                d_M [(size_t)q * M_DIM + myd]      = hnw;
            }
            gir = ngir; giz = ngiz; gin = ngin;
        }

        // save writeback state for next step's hn window
        pq = q; phas = has; ptb = tb;
    }

    // final-step d_H writeback
    if (pq >= 0 && c == ((T_STEPS - 1) & (CSZ - 1))) {
        float hv_out = phas ? ldcg_f(&d_M[(size_t)pq * M_DIM + tid])
                            : hn_sm[ptb][tid];
        d_H[(size_t)(T_STEPS - 1) * M_DIM + tid] = hv_out;
    }

    CLUSTER_SYNC();   // keep SMEM alive until all peers are done
}

extern "C" void kernel_launch(void* const* d_in, const int* in_sizes, int n_in,
                              void* d_out, int out_size)
{
    const float* X    = (const float*)d_in[0];
    const float* h0   = (const float*)d_in[1];
    const float* W_ih = (const float*)d_in[2];
    const float* W_hh = (const float*)d_in[3];
    const float* b_ih = (const float*)d_in[4];
    const float* b_hh = (const float*)d_in[5];
    const float* C_w  = (const float*)d_in[6];
    const float* C_b  = (const float*)d_in[7];
    const float* V_w  = (const float*)d_in[8];
    const float* V_b  = (const float*)d_in[9];
    float* Y = (float*)d_out;

    float* Gi; cudaGetSymbolAddress((void**)&Gi, d_Gi);
    float* H;  cudaGetSymbolAddress((void**)&H,  d_H);

    // 1) Gi = X @ W_ih^T + b_ih
    {
        dim3 blk(32, 32), grid(G3 / 32, T_STEPS / 32);
        gemm32_nt<<<grid, blk>>>(X, W_ih, b_ih, Gi, T_STEPS, G3, N_DIM);
    }
    // 2) clustered recurrent loop
    {
        const int smem = 2 * DPC * M_DIM * (int)sizeof(float);   // 131072
        cudaFuncSetAttribute(dmm_rec, cudaFuncAttributeNonPortableClusterSizeAllowed, 1);
        cudaFuncSetAttribute(dmm_rec, cudaFuncAttributeMaxDynamicSharedMemorySize, smem);
        cudaLaunchConfig_t cfg = {};
        cfg.gridDim  = dim3(CSZ, 1, 1);
        cfg.blockDim = dim3(NTHR, 1, 1);
        cfg.dynamicSmemBytes = smem;
        cfg.stream = 0;
        cudaLaunchAttribute at[1];
        at[0].id = cudaLaunchAttributeClusterDimension;
        at[0].val.clusterDim.x = CSZ;
        at[0].val.clusterDim.y = 1;
        at[0].val.clusterDim.z = 1;
        cfg.attrs = at;
        cfg.numAttrs = 1;
        cudaLaunchKernelEx(&cfg, dmm_rec, h0, W_hh, b_hh, C_w, C_b);
    }
    // 3) Y = H @ V_w^T + V_b
    {
        dim3 blk(32, 32), grid(L_OUT / 32, T_STEPS / 32);
        gemm32_nt<<<grid, blk>>>(H, V_w, V_b, Y, T_STEPS, L_OUT, M_DIM);
    }
}

// round 12
// speedup vs baseline: 1.1358x; 1.1358x over previous
#include <cuda_runtime.h>
#include <cuda_bf16.h>
#include <math.h>

#define T_STEPS 16384
#define N_DIM   256
#define M_DIM   512
#define G3      1536   // 3*M
#define NADDR   512    // K_MEM+1
#define L_OUT   256

#define CSZ     16     // cluster size (CTAs)
#define DPC     32     // h-dims per CTA (512/16)
#define NTHR    512

// ---------------- device scratch (static, no allocation) ----------------
__device__ __align__(16) float d_Gi[T_STEPS * G3];     // X @ W_ih^T + b_ih
__device__ __align__(16) float d_H [T_STEPS * M_DIM];  // h_out history
__device__ __align__(16) float d_M [NADDR * M_DIM];    // memory rows (write-once)
__device__ __align__(16) float d_Gc[NADDR * G3];       // cached gh: [q][3*d + gate]
__device__ int d_dec[T_STEPS];                         // per-step memory-read record

// ---------------- helpers ----------------
__device__ __forceinline__ void stasync_u64(unsigned long long* lptr, unsigned long long* lmbar,
                                            unsigned rank, unsigned long long v) {
    unsigned la = (unsigned)__cvta_generic_to_shared(lptr);
    unsigned lm = (unsigned)__cvta_generic_to_shared(lmbar);
    unsigned ra, rm;
    asm volatile("mapa.shared::cluster.u32 %0, %1, %2;" : "=r"(ra) : "r"(la), "r"(rank));
    asm volatile("mapa.shared::cluster.u32 %0, %1, %2;" : "=r"(rm) : "r"(lm), "r"(rank));
    asm volatile("st.async.weak.shared::cluster.mbarrier::complete_tx::bytes.b64 [%0], %1, [%2];"
                 :: "r"(ra), "l"(v), "r"(rm) : "memory");
}
// bulk SMEM->remote-SMEM copy, completion tx-accounted on the REMOTE mbarrier
__device__ __forceinline__ void bulk_s2s(float* ldst, const float* lsrc,
                                         unsigned long long* lmbar,
                                         unsigned rank, unsigned bytes) {
    unsigned ld = (unsigned)__cvta_generic_to_shared(ldst);
    unsigned ls = (unsigned)__cvta_generic_to_shared(lsrc);
    unsigned lm = (unsigned)__cvta_generic_to_shared(lmbar);
    unsigned rd, rm;
    asm volatile("mapa.shared::cluster.u32 %0, %1, %2;" : "=r"(rd) : "r"(ld), "r"(rank));
    asm volatile("mapa.shared::cluster.u32 %0, %1, %2;" : "=r"(rm) : "r"(lm), "r"(rank));
    asm volatile("cp.async.bulk.shared::cluster.shared::cta.mbarrier::complete_tx::bytes "
                 "[%0], [%1], %2, [%3];"
                 :: "r"(rd), "r"(ls), "r"(bytes), "r"(rm) : "memory");
}
__device__ __forceinline__ void mbar_init(unsigned long long* m, unsigned cnt) {
    unsigned a = (unsigned)__cvta_generic_to_shared(m);
    asm volatile("mbarrier.init.shared.b64 [%0], %1;" :: "r"(a), "r"(cnt) : "memory");
}
__device__ __forceinline__ void mbar_expect_tx(unsigned long long* m, unsigned bytes) {
    unsigned a = (unsigned)__cvta_generic_to_shared(m);
    asm volatile("mbarrier.arrive.expect_tx.shared.b64 _, [%0], %1;" :: "r"(a), "r"(bytes) : "memory");
}
__device__ __forceinline__ void mbar_wait(unsigned long long* m, unsigned parity) {
    unsigned a = (unsigned)__cvta_generic_to_shared(m);
    unsigned done;
    asm volatile("{\n\t.reg .pred p;\n\t"
                 "mbarrier.try_wait.parity.acquire.cta.shared::cta.b64 p, [%1], %2;\n\t"
                 "selp.b32 %0, 1, 0, p;\n\t}"
                 : "=r"(done) : "r"(a), "r"(parity) : "memory");
    if (!done) {
        asm volatile("{\n\t.reg .pred P1;\n\t"
                     "WL_%=:\n\t"
                     "mbarrier.try_wait.parity.acquire.cta.shared::cta.b64 P1, [%0], %1, 0x989680;\n\t"
                     "@P1 bra.uni WD_%=;\n\t"
                     "bra.uni WL_%=;\n\t"
                     "WD_%=:\n\t}"
                     :: "r"(a), "r"(parity) : "memory");
    }
}
#define CLUSTER_SYNC() do { \
    asm volatile("barrier.cluster.arrive.aligned;" ::: "memory"); \
    asm volatile("barrier.cluster.wait.aligned;"   ::: "memory"); } while (0)

// lexicographic u64 max over lanes via two integer REDUX (exact, same winner
// as a shfl-based u64 max tree): max hi, then max lo among hi-winners.
__device__ __forceinline__ unsigned long long warp_max_key(unsigned long long k) {
    unsigned hi = (unsigned)(k >> 32);
    unsigned lo = (unsigned)k;
    unsigned mhi = __reduce_max_sync(0xFFFFFFFFu, hi);
    unsigned mlo = __reduce_max_sync(0xFFFFFFFFu, (hi == mhi) ? lo : 0u);
    return ((unsigned long long)mhi << 32) | mlo;
}

// ---------------- textbook 32x32 tiled NT GEMM (known good) ----------------
__global__ __launch_bounds__(1024) void gemm32_nt(
    const float* __restrict__ A, const float* __restrict__ B,
    const float* __restrict__ bias, float* __restrict__ C,
    int M, int N, int K)
{
    __shared__ float As[32][33];
    __shared__ float Bs[32][33];
    const int bm = blockIdx.y * 32;
    const int bn = blockIdx.x * 32;
    const int tx = threadIdx.x;
    const int ty = threadIdx.y;
    float acc = 0.f;
    for (int k0 = 0; k0 < K; k0 += 32) {
        As[ty][tx] = A[(size_t)(bm + ty) * K + k0 + tx];
        Bs[ty][tx] = B[(size_t)(bn + ty) * K + k0 + tx];
        __syncthreads();
        #pragma unroll
        for (int k = 0; k < 32; k++)
            acc = fmaf(As[ty][k], Bs[tx][k], acc);
        __syncthreads();
    }
    C[(size_t)(bm + ty) * N + bn + tx] = acc + bias[bn + tx];
}

// ---------------- post-pass: fill d_H rows recorded as memory reads ----------------
__global__ __launch_bounds__(M_DIM) void dmm_fixup(void) {
    const int t = blockIdx.x;
    const int q = d_dec[t];
    if (q >= 0)
        d_H[(size_t)t * M_DIM + threadIdx.x] = d_M[(size_t)q * M_DIM + threadIdx.x];
}

// ---------------- clustered recurrent kernel ----------------
// Round-10 critical-path ordering (logits -> key send -> spec in key-wait shadow)
// + REDUX key reduces + DEFERRED d_H writeback: in-loop the duty CTA only stores
// hn from SMEM (has=0) or records q in d_dec (has=1); a post-pass gathers d_M
// rows. All per-value arithmetic verbatim -> trajectory bit-identical.
__global__ __launch_bounds__(NTHR, 1) void dmm_rec(
    const float* __restrict__ h0,
    const float* __restrict__ W_hh,
    const float* __restrict__ b_hh,
    const float* __restrict__ C_w,
    const float* __restrict__ C_b)
{
    extern __shared__ float W_sm[];                 // [2*DPC][512]: z rows, n rows
    __shared__ __align__(16) float hn_sm[2][M_DIM]; // bulk-copy target (double buffer)
    __shared__ __align__(16) float stage_sm[2][DPC];// local h_new slice (bulk source)
    __shared__ unsigned long long wkey_sm[16];
    __shared__ unsigned long long ckey_sm[CSZ];     // st.async target
    __shared__ unsigned char written_w[16][NADDR];  // per-warp replicas of 'written'
    __shared__ unsigned long long mbar_hn, mbar_key;

    const int c   = blockIdx.x;                     // cluster rank (single cluster)
    const int tid = threadIdx.x;
    const int w   = tid >> 5;
    const int l   = tid & 31;
    const int ml  = l & 15;
    const int d0  = DPC * c + w;
    const int d1  = DPC * c + 16 + w;
    const int myd = (l < 16) ? d0 : d1;

    // ---- one-time init ----
    for (int idx = tid; idx < 2 * DPC * M_DIM; idx += NTHR) {
        int g   = idx >> 14;
        int rem = idx & 16383;
        int lr  = rem >> 9;
        int col = rem & 511;
        W_sm[idx] = W_hh[(size_t)((g + 1) * M_DIM + DPC * c + lr) * M_DIM + col];
    }
    for (int idx = tid; idx < 16 * NADDR; idx += NTHR)
        written_w[idx >> 9][idx & 511] = 0;
    if (tid == 0) {
        mbar_init(&mbar_hn, 1);
        mbar_init(&mbar_key, 1);
        asm volatile("fence.mbarrier_init.release.cluster;" ::: "memory");
    }

    float4 wr0[4], wr1[4], cw0[4], cw1[4];
    #pragma unroll
    for (int cch = 0; cch < 4; cch++) {
        wr0[cch] = *(const float4*)&W_hh[(size_t)d0 * M_DIM + cch * 128 + 4 * l];
        wr1[cch] = *(const float4*)&W_hh[(size_t)d1 * M_DIM + cch * 128 + 4 * l];
        cw0[cch] = *(const float4*)&C_w [(size_t)d0 * M_DIM + cch * 128 + 4 * l];
        cw1[cch] = *(const float4*)&C_w [(size_t)d1 * M_DIM + cch * 128 + 4 * l];
    }
    const float cb0 = C_b[d0], cb1 = C_b[d1];
    const float bhr = b_hh[myd], bhz = b_hh[M_DIM + myd], bhn = b_hh[2 * M_DIM + myd];

    // ---- bootstrap: spec dots on h0 ----
    if (tid < M_DIM) hn_sm[1][tid] = h0[tid];
    __syncthreads();

    float4 nv[4];
    #pragma unroll
    for (int cch = 0; cch < 4; cch++) nv[cch] = *(const float4*)&hn_sm[1][cch * 128 + 4 * l];

    auto chain_sm = [&](const float* __restrict__ row) -> float {
        float acc = 0.f;
        #pragma unroll
        for (int cch = 0; cch < 4; cch++) {
            float4 wv = *(const float4*)&row[cch * 128 + 4 * l];
            acc = fmaf(wv.x, nv[cch].x, fmaf(wv.y, nv[cch].y,
                  fmaf(wv.z, nv[cch].z, fmaf(wv.w, nv[cch].w, acc))));
        }
        return acc;
    };
    auto chain_rg = [&](const float4* wreg) -> float {
        float acc = 0.f;
        #pragma unroll
        for (int cch = 0; cch < 4; cch++) {
            acc = fmaf(wreg[cch].x, nv[cch].x, fmaf(wreg[cch].y, nv[cch].y,
                  fmaf(wreg[cch].z, nv[cch].z, fmaf(wreg[cch].w, nv[cch].w, acc))));
        }
        return acc;
    };
    auto tree = [&](float acc) -> float {
        #pragma unroll
        for (int o = 16; o > 0; o >>= 1) acc += __shfl_xor_sync(0xFFFFFFFFu, acc, o);
        return acc;
    };

    float s0z = tree(chain_sm(&W_sm[(0 * DPC + w)      * M_DIM]));
    float s0n = tree(chain_sm(&W_sm[(1 * DPC + w)      * M_DIM]));
    float s1z = tree(chain_sm(&W_sm[(0 * DPC + 16 + w) * M_DIM]));
    float s1n = tree(chain_sm(&W_sm[(1 * DPC + 16 + w) * M_DIM]));
    float s0r = tree(chain_rg(wr0));
    float s1r = tree(chain_rg(wr1));

    float gr = (l < 16) ? s0r : s1r;
    float gz = (l < 16) ? s0z : s1z;
    float gn = (l < 16) ? s0n : s1n;
    float hp = hn_sm[1][myd];
    float gir = 0.f, giz = 0.f, gin = 0.f;
    if (ml == 0) {
        gir = __ldg(&d_Gi[myd]);
        giz = __ldg(&d_Gi[M_DIM + myd]);
        gin = __ldg(&d_Gi[2 * M_DIM + myd]);
    }

    // previous-step writeback state
    int pq = -1, phas = 0, ptb = 0;

    __syncthreads();
    CLUSTER_SYNC();   // mbarriers + SMEM init visible cluster-wide before async traffic

    for (int t = 0; t < T_STEPS; t++) {
        const int tb = t & 1;
        const unsigned par = (unsigned)(t & 1);

        // ---------- gates (lanes 0,16), verbatim expressions ----------
        float hnewv = 0.f;
        if (ml == 0) {
            float hr = gr + bhr, hz = gz + bhz, hn = gn + bhn;
            float rg = 1.f / (1.f + expf(-(gir + hr)));
            float zg = 1.f / (1.f + expf(-(giz + hz)));
            float ng = tanhf(gin + rg * hn);
            hnewv = (1.f - zg) * ng + zg * hp;
            stage_sm[tb][w + ((l < 16) ? 0 : 16)] = hnewv;   // contiguous 128B slice
        }
        const float v0 = __shfl_sync(0xFFFFFFFFu, hnewv, 0);
        const float v1 = __shfl_sync(0xFFFFFFFFu, hnewv, 16);
        __syncthreads();   // stage slice complete

        // ---------- bulk-deliver slice to all 16 ranks (warp 0, 16 x 128B) ----------
        if (tid == 0) mbar_expect_tx(&mbar_hn, M_DIM * 4u);     // 2048 B per phase
        if (w == 0 && l < CSZ) {
            asm volatile("fence.proxy.async.shared::cta;" ::: "memory");
            bulk_s2s(&hn_sm[tb][DPC * c], &stage_sm[tb][0], &mbar_hn,
                     (unsigned)l, DPC * 4u);
        }

        // ---------- hn-flight window: prev-step d_H duty (no L2 reads) + Gi prefetch ----------
        if (pq >= 0 && c == ((t - 1) & (CSZ - 1))) {
            if (!phas) d_H[(size_t)(t - 1) * M_DIM + tid] = hn_sm[ptb][tid];
            if (tid == 0) d_dec[t - 1] = phas ? pq : -1;
        }
        float ngir = 0.f, ngiz = 0.f, ngin = 0.f;
        if (ml == 0 && t + 1 < T_STEPS) {
            const float* g = &d_Gi[(size_t)(t + 1) * G3];
            ngir = __ldg(&g[myd]);
            ngiz = __ldg(&g[M_DIM + myd]);
            ngin = __ldg(&g[2 * M_DIM + myd]);
        }

        mbar_wait(&mbar_hn, par);   // all 16 slices landed locally

        // ---------- logits for d0,d1 (critical path: straight to key send) ----------
        #pragma unroll
        for (int cch = 0; cch < 4; cch++) nv[cch] = *(const float4*)&hn_sm[tb][cch * 128 + 4 * l];
        float acc0 = tree(chain_rg(cw0));
        float acc1 = tree(chain_rg(cw1));
        if (l == 0) {
            unsigned int u0 = __float_as_uint(acc0 + cb0);
            u0 ^= (u0 & 0x80000000u) ? 0xFFFFFFFFu : 0x80000000u;
            unsigned long long k0 = ((unsigned long long)u0 << 32) | (unsigned int)(1023 - d0);
            unsigned int u1 = __float_as_uint(acc1 + cb1);
            u1 ^= (u1 & 0x80000000u) ? 0xFFFFFFFFu : 0x80000000u;
            unsigned long long k1 = ((unsigned long long)u1 << 32) | (unsigned int)(1023 - d1);
            wkey_sm[w] = (k0 > k1) ? k0 : k1;
        }
        __syncthreads();
        if (tid == 0) mbar_expect_tx(&mbar_key, CSZ * 8u);      // 128 B per phase
        if (w == 0) {
            unsigned long long best = warp_max_key((l < 16) ? wkey_sm[l] : 0ull);
            if (l < CSZ) stasync_u64(&ckey_sm[c], &mbar_key, (unsigned)l, best);
        }

        // ---------- speculative W_hh @ h_new fills the key-wait shadow ----------
        s0z = tree(chain_sm(&W_sm[(0 * DPC + w)      * M_DIM]));
        s0n = tree(chain_sm(&W_sm[(1 * DPC + w)      * M_DIM]));
        s1z = tree(chain_sm(&W_sm[(0 * DPC + 16 + w) * M_DIM]));
        s1n = tree(chain_sm(&W_sm[(1 * DPC + 16 + w) * M_DIM]));
        s0r = tree(chain_rg(wr0));
        s1r = tree(chain_rg(wr1));

        mbar_wait(&mbar_key, par);   // all 16 CTA keys landed locally

        // ---------- per-warp redundant decision (REDUX, no syncthreads) ----------
        unsigned long long best = warp_max_key((l < CSZ) ? ckey_sm[l] : 0ull);
        const int q   = 1023 - (int)(best & 0xFFFFFFFFull);
        const int has = (q > 0) && (written_w[w][q] != 0);
        __syncwarp();
        if (l == 0 && q > 0) written_w[w][q] = 1;

        // ---------- select next gate inputs + cache maintenance ----------
        const float s_r = (l < 16) ? s0r : s1r;
        const float s_z = (l < 16) ? s0z : s1z;
        const float s_n = (l < 16) ? s0n : s1n;
        const float hnw = (l < 16) ? v0  : v1;

        if (ml == 0) {
            if (has) {   // CTA-private cached slices (immutable after write)
                gr = __ldg(&d_Gc[(size_t)q * G3 + 3 * myd + 0]);
                gz = __ldg(&d_Gc[(size_t)q * G3 + 3 * myd + 1]);
                gn = __ldg(&d_Gc[(size_t)q * G3 + 3 * myd + 2]);
                hp = __ldg(&d_M [(size_t)q * M_DIM + myd]);
            } else {
                gr = s_r; gz = s_z; gn = s_n; hp = hnw;
            }
            if (!has && q > 0) {
                d_Gc[(size_t)q * G3 + 3 * myd + 0] = s_r;
                d_Gc[(size_t)q * G3 + 3 * myd + 1] = s_z;
                d_Gc[(size_t)q * G3 + 3 * myd + 2] = s_n;
                d_M [(size_t)q * M_DIM + myd]      = hnw;
            }
            gir = ngir; giz = ngiz; gin = ngin;
        }

        // save writeback state for next step's hn window
        pq = q; phas = has; ptb = tb;
    }

    // final-step d_H duty
    if (pq >= 0 && c == ((T_STEPS - 1) & (CSZ - 1))) {
        if (!phas) d_H[(size_t)(T_STEPS - 1) * M_DIM + tid] = hn_sm[ptb][tid];
        if (tid == 0) d_dec[T_STEPS - 1] = phas ? pq : -1;
    }

    CLUSTER_SYNC();   // keep SMEM alive until all peers are done
}

extern "C" void kernel_launch(void* const* d_in, const int* in_sizes, int n_in,
                              void* d_out, int out_size)
{
    const float* X    = (const float*)d_in[0];
    const float* h0   = (const float*)d_in[1];
    const float* W_ih = (const float*)d_in[2];
    const float* W_hh = (const float*)d_in[3];
    const float* b_ih = (const float*)d_in[4];
    const float* b_hh = (const float*)d_in[5];
    const float* C_w  = (const float*)d_in[6];
    const float* C_b  = (const float*)d_in[7];
    const float* V_w  = (const float*)d_in[8];
    const float* V_b  = (const float*)d_in[9];
    float* Y = (float*)d_out;

    float* Gi; cudaGetSymbolAddress((void**)&Gi, d_Gi);
    float* H;  cudaGetSymbolAddress((void**)&H,  d_H);

    // 1) Gi = X @ W_ih^T + b_ih
    {
        dim3 blk(32, 32), grid(G3 / 32, T_STEPS / 32);
        gemm32_nt<<<grid, blk>>>(X, W_ih, b_ih, Gi, T_STEPS, G3, N_DIM);
    }
    // 2) clustered recurrent loop
    {
        const int smem = 2 * DPC * M_DIM * (int)sizeof(float);   // 131072
        cudaFuncSetAttribute(dmm_rec, cudaFuncAttributeNonPortableClusterSizeAllowed, 1);
        cudaFuncSetAttribute(dmm_rec, cudaFuncAttributeMaxDynamicSharedMemorySize, smem);
        cudaLaunchConfig_t cfg = {};
        cfg.gridDim  = dim3(CSZ, 1, 1);
        cfg.blockDim = dim3(NTHR, 1, 1);
        cfg.dynamicSmemBytes = smem;
        cfg.stream = 0;
        cudaLaunchAttribute at[1];
        at[0].id = cudaLaunchAttributeClusterDimension;
        at[0].val.clusterDim.x = CSZ;
        at[0].val.clusterDim.y = 1;
        at[0].val.clusterDim.z = 1;
        cfg.attrs = at;
        cfg.numAttrs = 1;
        cudaLaunchKernelEx(&cfg, dmm_rec, h0, W_hh, b_hh, C_w, C_b);
    }
    // 3) fill memory-read history rows from d_M (write-once, final state valid)
    dmm_fixup<<<T_STEPS, M_DIM>>>();
    // 4) Y = H @ V_w^T + V_b
    {
        dim3 blk(32, 32), grid(L_OUT / 32, T_STEPS / 32);
        gemm32_nt<<<grid, blk>>>(H, V_w, V_b, Y, T_STEPS, L_OUT, M_DIM);
    }
}

// round 13
// speedup vs baseline: 1.3734x; 1.2092x over previous
#include <cuda_runtime.h>
#include <cuda_bf16.h>
#include <math.h>

#define T_STEPS 16384
#define N_DIM   256
#define M_DIM   512
#define G3      1536   // 3*M
#define NADDR   512    // K_MEM+1
#define L_OUT   256

#define CSZ     16     // cluster size (CTAs)
#define DPC     32     // h-dims per CTA (512/16)
#define NTHR    512

// ---------------- device scratch (static, no allocation) ----------------
__device__ __align__(16) float  d_Gi[T_STEPS * G3];      // X @ W_ih^T + b_ih
__device__ __align__(16) float  d_H [T_STEPS * M_DIM];   // h_out history
__device__ __align__(16) float  d_M [NADDR * M_DIM];     // memory rows (write-once)
__device__ __align__(16) float4 d_Gc4[NADDR * M_DIM];    // cache: (gr,gz,gn,hp) per [q][dim]
__device__ int d_dec[T_STEPS];                           // per-step memory-read record

// ---------------- helpers ----------------
__device__ __forceinline__ void stasync_u64(unsigned long long* lptr, unsigned long long* lmbar,
                                            unsigned rank, unsigned long long v) {
    unsigned la = (unsigned)__cvta_generic_to_shared(lptr);
    unsigned lm = (unsigned)__cvta_generic_to_shared(lmbar);
    unsigned ra, rm;
    asm volatile("mapa.shared::cluster.u32 %0, %1, %2;" : "=r"(ra) : "r"(la), "r"(rank));
    asm volatile("mapa.shared::cluster.u32 %0, %1, %2;" : "=r"(rm) : "r"(lm), "r"(rank));
    asm volatile("st.async.weak.shared::cluster.mbarrier::complete_tx::bytes.b64 [%0], %1, [%2];"
                 :: "r"(ra), "l"(v), "r"(rm) : "memory");
}
__device__ __forceinline__ void bulk_s2s(float* ldst, const float* lsrc,
                                         unsigned long long* lmbar,
                                         unsigned rank, unsigned bytes) {
    unsigned ld = (unsigned)__cvta_generic_to_shared(ldst);
    unsigned ls = (unsigned)__cvta_generic_to_shared(lsrc);
    unsigned lm = (unsigned)__cvta_generic_to_shared(lmbar);
    unsigned rd, rm;
    asm volatile("mapa.shared::cluster.u32 %0, %1, %2;" : "=r"(rd) : "r"(ld), "r"(rank));
    asm volatile("mapa.shared::cluster.u32 %0, %1, %2;" : "=r"(rm) : "r"(lm), "r"(rank));
    asm volatile("cp.async.bulk.shared::cluster.shared::cta.mbarrier::complete_tx::bytes "
                 "[%0], [%1], %2, [%3];"
                 :: "r"(rd), "r"(ls), "r"(bytes), "r"(rm) : "memory");
}
__device__ __forceinline__ void mbar_init(unsigned long long* m, unsigned cnt) {
    unsigned a = (unsigned)__cvta_generic_to_shared(m);
    asm volatile("mbarrier.init.shared.b64 [%0], %1;" :: "r"(a), "r"(cnt) : "memory");
}
__device__ __forceinline__ void mbar_expect_tx(unsigned long long* m, unsigned bytes) {
    unsigned a = (unsigned)__cvta_generic_to_shared(m);
    asm volatile("mbarrier.arrive.expect_tx.shared.b64 _, [%0], %1;" :: "r"(a), "r"(bytes) : "memory");
}
__device__ __forceinline__ void mbar_wait(unsigned long long* m, unsigned parity) {
    unsigned a = (unsigned)__cvta_generic_to_shared(m);
    unsigned done;
    asm volatile("{\n\t.reg .pred p;\n\t"
                 "mbarrier.try_wait.parity.acquire.cta.shared::cta.b64 p, [%1], %2;\n\t"
                 "selp.b32 %0, 1, 0, p;\n\t}"
                 : "=r"(done) : "r"(a), "r"(parity) : "memory");
    if (!done) {
        asm volatile("{\n\t.reg .pred P1;\n\t"
                     "WL_%=:\n\t"
                     "mbarrier.try_wait.parity.acquire.cta.shared::cta.b64 P1, [%0], %1, 0x989680;\n\t"
                     "@P1 bra.uni WD_%=;\n\t"
                     "bra.uni WL_%=;\n\t"
                     "WD_%=:\n\t}"
                     :: "r"(a), "r"(parity) : "memory");
    }
}
#define CLUSTER_SYNC() do { \
    asm volatile("barrier.cluster.arrive.aligned;" ::: "memory"); \
    asm volatile("barrier.cluster.wait.aligned;"   ::: "memory"); } while (0)

__device__ __forceinline__ unsigned long long warp_max_key(unsigned long long k) {
    unsigned hi = (unsigned)(k >> 32);
    unsigned lo = (unsigned)k;
    unsigned mhi = __reduce_max_sync(0xFFFFFFFFu, hi);
    unsigned mlo = __reduce_max_sync(0xFFFFFFFFu, (hi == mhi) ? lo : 0u);
    return ((unsigned long long)mhi << 32) | mlo;
}

// ---------------- textbook 32x32 tiled NT GEMM (known good) ----------------
__global__ __launch_bounds__(1024) void gemm32_nt(
    const float* __restrict__ A, const float* __restrict__ B,
    const float* __restrict__ bias, float* __restrict__ C,
    int M, int N, int K)
{
    __shared__ float As[32][33];
    __shared__ float Bs[32][33];
    const int bm = blockIdx.y * 32;
    const int bn = blockIdx.x * 32;
    const int tx = threadIdx.x;
    const int ty = threadIdx.y;
    float acc = 0.f;
    for (int k0 = 0; k0 < K; k0 += 32) {
        As[ty][tx] = A[(size_t)(bm + ty) * K + k0 + tx];
        Bs[ty][tx] = B[(size_t)(bn + ty) * K + k0 + tx];
        __syncthreads();
        #pragma unroll
        for (int k = 0; k < 32; k++)
            acc = fmaf(As[ty][k], Bs[tx][k], acc);
        __syncthreads();
    }
    C[(size_t)(bm + ty) * N + bn + tx] = acc + bias[bn + tx];
}

// ---------------- post-pass: fill d_H rows recorded as memory reads ----------------
__global__ __launch_bounds__(M_DIM) void dmm_fixup(void) {
    const int t = blockIdx.x;
    const int q = d_dec[t];
    if (q >= 0)
        d_H[(size_t)t * M_DIM + threadIdx.x] = d_M[(size_t)q * M_DIM + threadIdx.x];
}

// ---------------- clustered recurrent kernel (conditional speculation) ----------------
__global__ __launch_bounds__(NTHR, 1) void dmm_rec(
    const float* __restrict__ h0,
    const float* __restrict__ W_hh,
    const float* __restrict__ b_hh,
    const float* __restrict__ C_w,
    const float* __restrict__ C_b)
{
    extern __shared__ float W_sm[];                 // [2*DPC][512]: z rows, n rows
    __shared__ __align__(16) float hn_sm[2][M_DIM];
    __shared__ __align__(16) float stage_sm[2][DPC];
    __shared__ unsigned long long wkey_sm[16];
    __shared__ unsigned long long ckey_sm[CSZ];
    __shared__ unsigned char written_w[16][NADDR];
    __shared__ unsigned long long mbar_hn, mbar_key;

    const int c   = blockIdx.x;
    const int tid = threadIdx.x;
    const int w   = tid >> 5;
    const int l   = tid & 31;
    const int ml  = l & 15;
    const int d0  = DPC * c + w;
    const int d1  = DPC * c + 16 + w;
    const int myd = (l < 16) ? d0 : d1;

    for (int idx = tid; idx < 2 * DPC * M_DIM; idx += NTHR) {
        int g   = idx >> 14;
        int rem = idx & 16383;
        int lr  = rem >> 9;
        int col = rem & 511;
        W_sm[idx] = W_hh[(size_t)((g + 1) * M_DIM + DPC * c + lr) * M_DIM + col];
    }
    for (int idx = tid; idx < 16 * NADDR; idx += NTHR)
        written_w[idx >> 9][idx & 511] = 0;
    if (tid == 0) {
        mbar_init(&mbar_hn, 1);
        mbar_init(&mbar_key, 1);
        asm volatile("fence.mbarrier_init.release.cluster;" ::: "memory");
    }

    float4 wr0[4], wr1[4], cw0[4], cw1[4];
    #pragma unroll
    for (int cch = 0; cch < 4; cch++) {
        wr0[cch] = *(const float4*)&W_hh[(size_t)d0 * M_DIM + cch * 128 + 4 * l];
        wr1[cch] = *(const float4*)&W_hh[(size_t)d1 * M_DIM + cch * 128 + 4 * l];
        cw0[cch] = *(const float4*)&C_w [(size_t)d0 * M_DIM + cch * 128 + 4 * l];
        cw1[cch] = *(const float4*)&C_w [(size_t)d1 * M_DIM + cch * 128 + 4 * l];
    }
    const float cb0 = C_b[d0], cb1 = C_b[d1];
    const float bhr = b_hh[myd], bhz = b_hh[M_DIM + myd], bhn = b_hh[2 * M_DIM + myd];

    if (tid < M_DIM) hn_sm[1][tid] = h0[tid];
    __syncthreads();

    float4 nv[4];
    #pragma unroll
    for (int cch = 0; cch < 4; cch++) nv[cch] = *(const float4*)&hn_sm[1][cch * 128 + 4 * l];

    auto chain_sm = [&](const float* __restrict__ row) -> float {
        float acc = 0.f;
        #pragma unroll
        for (int cch = 0; cch < 4; cch++) {
            float4 wv = *(const float4*)&row[cch * 128 + 4 * l];
            acc = fmaf(wv.x, nv[cch].x, fmaf(wv.y, nv[cch].y,
                  fmaf(wv.z, nv[cch].z, fmaf(wv.w, nv[cch].w, acc))));
        }
        return acc;
    };
    auto chain_rg = [&](const float4* wreg) -> float {
        float acc = 0.f;
        #pragma unroll
        for (int cch = 0; cch < 4; cch++) {
            acc = fmaf(wreg[cch].x, nv[cch].x, fmaf(wreg[cch].y, nv[cch].y,
                  fmaf(wreg[cch].z, nv[cch].z, fmaf(wreg[cch].w, nv[cch].w, acc))));
        }
        return acc;
    };
    auto tree = [&](float acc) -> float {
        #pragma unroll
        for (int o = 16; o > 0; o >>= 1) acc += __shfl_xor_sync(0xFFFFFFFFu, acc, o);
        return acc;
    };

    // persistent gate inputs (bootstrap = spec on h0, verbatim chains)
    float grv, gzv, gnv;
    {
        float s0z = tree(chain_sm(&W_sm[(0 * DPC + w)      * M_DIM]));
        float s0n = tree(chain_sm(&W_sm[(1 * DPC + w)      * M_DIM]));
        float s1z = tree(chain_sm(&W_sm[(0 * DPC + 16 + w) * M_DIM]));
        float s1n = tree(chain_sm(&W_sm[(1 * DPC + 16 + w) * M_DIM]));
        float s0r = tree(chain_rg(wr0));
        float s1r = tree(chain_rg(wr1));
        grv = (l < 16) ? s0r : s1r;
        gzv = (l < 16) ? s0z : s1z;
        gnv = (l < 16) ? s0n : s1n;
    }
    float hp = hn_sm[1][myd];
    float gir = 0.f, giz = 0.f, gin = 0.f;
    if (ml == 0) {
        gir = __ldg(&d_Gi[myd]);
        giz = __ldg(&d_Gi[M_DIM + myd]);
        gin = __ldg(&d_Gi[2 * M_DIM + myd]);
    }

    int pq = -1, phas = 0, ptb = 0;

    __syncthreads();
    CLUSTER_SYNC();

    for (int t = 0; t < T_STEPS; t++) {
        const int tb = t & 1;
        const unsigned par = (unsigned)(t & 1);

        float hnewv = 0.f;
        if (ml == 0) {
            float hr = grv + bhr, hz = gzv + bhz, hn = gnv + bhn;
            float rg = 1.f / (1.f + expf(-(gir + hr)));
            float zg = 1.f / (1.f + expf(-(giz + hz)));
            float ng = tanhf(gin + rg * hn);
            hnewv = (1.f - zg) * ng + zg * hp;
            stage_sm[tb][w + ((l < 16) ? 0 : 16)] = hnewv;
        }
        const float v0 = __shfl_sync(0xFFFFFFFFu, hnewv, 0);
        const float v1 = __shfl_sync(0xFFFFFFFFu, hnewv, 16);
        __syncthreads();

        if (tid == 0) mbar_expect_tx(&mbar_hn, M_DIM * 4u);
        if (w == 0 && l < CSZ) {
            asm volatile("fence.proxy.async.shared::cta;" ::: "memory");
            bulk_s2s(&hn_sm[tb][DPC * c], &stage_sm[tb][0], &mbar_hn,
                     (unsigned)l, DPC * 4u);
        }

        if (pq >= 0 && c == ((t - 1) & (CSZ - 1))) {
            if (!phas) d_H[(size_t)(t - 1) * M_DIM + tid] = hn_sm[ptb][tid];
            if (tid == 0) d_dec[t - 1] = phas ? pq : -1;
        }
        float ngir = 0.f, ngiz = 0.f, ngin = 0.f;
        if (ml == 0 && t + 1 < T_STEPS) {
            const float* g = &d_Gi[(size_t)(t + 1) * G3];
            ngir = __ldg(&g[myd]);
            ngiz = __ldg(&g[M_DIM + myd]);
            ngin = __ldg(&g[2 * M_DIM + myd]);
        }

        mbar_wait(&mbar_hn, par);

        #pragma unroll
        for (int cch = 0; cch < 4; cch++) nv[cch] = *(const float4*)&hn_sm[tb][cch * 128 + 4 * l];
        float acc0 = tree(chain_rg(cw0));
        float acc1 = tree(chain_rg(cw1));
        if (l == 0) {
            unsigned int u0 = __float_as_uint(acc0 + cb0);
            u0 ^= (u0 & 0x80000000u) ? 0xFFFFFFFFu : 0x80000000u;
            unsigned long long k0 = ((unsigned long long)u0 << 32) | (unsigned int)(1023 - d0);
            unsigned int u1 = __float_as_uint(acc1 + cb1);
            u1 ^= (u1 & 0x80000000u) ? 0xFFFFFFFFu : 0x80000000u;
            unsigned long long k1 = ((unsigned long long)u1 << 32) | (unsigned int)(1023 - d1);
            wkey_sm[w] = (k0 > k1) ? k0 : k1;
        }
        __syncthreads();
        if (tid == 0) mbar_expect_tx(&mbar_key, CSZ * 8u);
        if (w == 0) {
            unsigned long long best = warp_max_key((l < 16) ? wkey_sm[l] : 0ull);
            if (l < CSZ) stasync_u64(&ckey_sm[c], &mbar_key, (unsigned)l, best);
        }

        mbar_wait(&mbar_key, par);

        unsigned long long best = warp_max_key((l < CSZ) ? ckey_sm[l] : 0ull);
        const int q   = 1023 - (int)(best & 0xFFFFFFFFull);
        const int has = (q > 0) && (written_w[w][q] != 0);
        __syncwarp();
        if (l == 0 && q > 0) written_w[w][q] = 1;

        const float hnw = (l < 16) ? v0 : v1;

        if (has) {
            if (ml == 0) {
                float4 g4 = __ldg(&d_Gc4[(size_t)q * M_DIM + myd]);
                grv = g4.x; gzv = g4.y; gnv = g4.z; hp = g4.w;
            }
        } else {
            float s0z = tree(chain_sm(&W_sm[(0 * DPC + w)      * M_DIM]));
            float s0n = tree(chain_sm(&W_sm[(1 * DPC + w)      * M_DIM]));
            float s1z = tree(chain_sm(&W_sm[(0 * DPC + 16 + w) * M_DIM]));
            float s1n = tree(chain_sm(&W_sm[(1 * DPC + 16 + w) * M_DIM]));
            float s0r = tree(chain_rg(wr0));
            float s1r = tree(chain_rg(wr1));
            const float s_r = (l < 16) ? s0r : s1r;
            const float s_z = (l < 16) ? s0z : s1z;
            const float s_n = (l < 16) ? s0n : s1n;
            if (ml == 0) {
                grv = s_r; gzv = s_z; gnv = s_n; hp = hnw;
                if (q > 0) {
                    d_Gc4[(size_t)q * M_DIM + myd] = make_float4(s_r, s_z, s_n, hnw);
                    d_M [(size_t)q * M_DIM + myd]  = hnw;
                }
            }
        }
        if (ml == 0) { gir = ngir; giz = ngiz; gin = ngin; }

        pq = q; phas = has; ptb = tb;
    }

    if (pq >= 0 && c == ((T_STEPS - 1) & (CSZ - 1))) {
        if (!phas) d_H[(size_t)(T_STEPS - 1) * M_DIM + tid] = hn_sm[ptb][tid];
        if (tid == 0) d_dec[T_STEPS - 1] = phas ? pq : -1;
    }

    CLUSTER_SYNC();
}

extern "C" void kernel_launch(void* const* d_in, const int* in_sizes, int n_in,
                              void* d_out, int out_size)
{
    const float* X    = (const float*)d_in[0];
    const float* h0   = (const float*)d_in[1];
    const float* W_ih = (const float*)d_in[2];
    const float* W_hh = (const float*)d_in[3];
    const float* b_ih = (const float*)d_in[4];
    const float* b_hh = (const float*)d_in[5];
    const float* C_w  = (const float*)d_in[6];
    const float* C_b  = (const float*)d_in[7];
    const float* V_w  = (const float*)d_in[8];
    const float* V_b  = (const float*)d_in[9];
    float* Y = (float*)d_out;

    float* Gi; cudaGetSymbolAddress((void**)&Gi, d_Gi);
    float* H;  cudaGetSymbolAddress((void**)&H,  d_H);

    {
        dim3 blk(32, 32), grid(G3 / 32, T_STEPS / 32);
        gemm32_nt<<<grid, blk>>>(X, W_ih, b_ih, Gi, T_STEPS, G3, N_DIM);
    }
    {
        const int smem = 2 * DPC * M_DIM * (int)sizeof(float);   // 131072
        cudaFuncSetAttribute(dmm_rec, cudaFuncAttributeNonPortableClusterSizeAllowed, 1);
        cudaFuncSetAttribute(dmm_rec, cudaFuncAttributeMaxDynamicSharedMemorySize, smem);
        cudaLaunchConfig_t cfg = {};
        cfg.gridDim  = dim3(CSZ, 1, 1);
        cfg.blockDim = dim3(NTHR, 1, 1);
        cfg.dynamicSmemBytes = smem;
        cfg.stream = 0;
        cudaLaunchAttribute at[1];
        at[0].id = cudaLaunchAttributeClusterDimension;
        at[0].val.clusterDim.x = CSZ;
        at[0].val.clusterDim.y = 1;
        at[0].val.clusterDim.z = 1;
        cfg.attrs = at;
        cfg.numAttrs = 1;
        cudaLaunchKernelEx(&cfg, dmm_rec, h0, W_hh, b_hh, C_w, C_b);
    }
    dmm_fixup<<<T_STEPS, M_DIM>>>();
    {
        dim3 blk(32, 32), grid(L_OUT / 32, T_STEPS / 32);
        gemm32_nt<<<grid, blk>>>(H, V_w, V_b, Y, T_STEPS, L_OUT, M_DIM);
    }
}